// round 1
// baseline (speedup 1.0000x reference)
#include <cuda_runtime.h>
#include <math.h>

#define B_    64
#define D_    512
#define S_    2048
#define K_    8
#define TWO_D 1024

// ---- scratch (static device globals; no runtime allocation) ----
__device__ float g_peT[TWO_D * S_];   // PE^T: [e][s]  (8 MB)
__device__ float g_p1 [S_ * D_];      // PE@W1^T + b1: [s][d] (4 MB)
__device__ float g_mean[B_ * D_];
__device__ float g_gb [B_ * D_];      // mean @ W1[:,D:2D]^T
__device__ float g_score[B_ * S_];
__device__ int   g_idx[B_ * K_];

// ---------------------------------------------------------------
// 1) PE table (transposed so the p1 GEMM sees an M-contiguous A)
// ---------------------------------------------------------------
__global__ void pe_fill_kernel() {
    int s = blockIdx.x * blockDim.x + threadIdx.x;  // 0..S-1
    int i = blockIdx.y;                              // 0..D-1 (pair index)
    float div = expf(-(float)(2 * i) * logf(10000.0f) / (float)TWO_D);
    float sv, cv;
    sincosf((float)s * div, &sv, &cv);
    g_peT[(size_t)(2 * i)     * S_ + s] = sv;
    g_peT[(size_t)(2 * i + 1) * S_ + s] = cv;
}

// ---------------------------------------------------------------
// 2) mean over sequence: one warp per (b,d) row, coalesced in s
// ---------------------------------------------------------------
__global__ void mean_kernel(const float* __restrict__ x) {
    int warp = (blockIdx.x * blockDim.x + threadIdx.x) >> 5;
    int lane = threadIdx.x & 31;
    const float* row = x + (size_t)warp * S_;
    float sum = 0.f;
    for (int i = lane; i < S_; i += 32) sum += row[i];
    #pragma unroll
    for (int off = 16; off > 0; off >>= 1)
        sum += __shfl_down_sync(0xffffffffu, sum, off);
    if (lane == 0) g_mean[warp] = sum * (1.0f / S_);
}

// ---------------------------------------------------------------
// 3) p1[s,d] = b1[d] + sum_e PE[s,e] * W1[d,e]   (M=2048,N=512,K=1024)
//    A = g_peT (K rows, M-contiguous), B = W1 (N rows, K-contiguous)
// ---------------------------------------------------------------
#define BM 128
#define BN 128
#define BK 16

__global__ __launch_bounds__(256) void p1_gemm_kernel(
    const float* __restrict__ W1, const float* __restrict__ b1)
{
    __shared__ float As[BK][BM];
    __shared__ float Bs[BK][132];

    int s0 = blockIdx.x * BM;   // grid.x = 16
    int d0 = blockIdx.y * BN;   // grid.y = 4
    int tid = threadIdx.x;
    int tx = tid & 15, ty = tid >> 4;

    float c[8][8];
    #pragma unroll
    for (int i = 0; i < 8; i++)
        #pragma unroll
        for (int j = 0; j < 8; j++) c[i][j] = 0.f;

    for (int k0 = 0; k0 < TWO_D; k0 += BK) {
        #pragma unroll
        for (int q = 0; q < 2; ++q) {
            int p = tid + q * 256;
            int e = p >> 5;
            int sc = (p & 31) << 2;
            float4 v = *(const float4*)(g_peT + (size_t)(k0 + e) * S_ + s0 + sc);
            *(float4*)(&As[e][sc]) = v;
        }
        #pragma unroll
        for (int q = 0; q < 2; ++q) {
            int p = tid + q * 256;
            int d = p >> 2;
            int e = (p & 3) << 2;
            float4 v = *(const float4*)(W1 + (size_t)(d0 + d) * TWO_D + k0 + e);
            Bs[e + 0][d] = v.x; Bs[e + 1][d] = v.y;
            Bs[e + 2][d] = v.z; Bs[e + 3][d] = v.w;
        }
        __syncthreads();
        #pragma unroll
        for (int kk = 0; kk < BK; ++kk) {
            float a[8], bb[8];
            #pragma unroll
            for (int i = 0; i < 8; i++) a[i] = As[kk][ty * 8 + i];
            #pragma unroll
            for (int j = 0; j < 8; j++) bb[j] = Bs[kk][tx * 8 + j];
            #pragma unroll
            for (int i = 0; i < 8; i++)
                #pragma unroll
                for (int j = 0; j < 8; j++)
                    c[i][j] = fmaf(a[i], bb[j], c[i][j]);
        }
        __syncthreads();
    }
    #pragma unroll
    for (int i = 0; i < 8; i++) {
        int s = s0 + ty * 8 + i;
        #pragma unroll
        for (int j = 0; j < 8; j++) {
            int d = d0 + tx * 8 + j;
            g_p1[(size_t)s * D_ + d] = c[i][j] + b1[d];
        }
    }
}

// ---------------------------------------------------------------
// 4) g[b,d] = sum_e mean[b,e] * W1[d, D+e]   (tiny, L2-resident)
// ---------------------------------------------------------------
__global__ void g_kernel(const float* __restrict__ W1) {
    __shared__ float sm[D_];
    int b = blockIdx.x;
    for (int i = threadIdx.x; i < D_; i += blockDim.x)
        sm[i] = g_mean[b * D_ + i];
    __syncthreads();
    int d = threadIdx.x;  // blockDim = 512
    const float4* w = (const float4*)(W1 + (size_t)d * TWO_D + D_);
    float acc = 0.f;
    #pragma unroll 4
    for (int e4 = 0; e4 < D_ / 4; e4++) {
        float4 v = w[e4];
        acc = fmaf(sm[4 * e4 + 0], v.x, acc);
        acc = fmaf(sm[4 * e4 + 1], v.y, acc);
        acc = fmaf(sm[4 * e4 + 2], v.z, acc);
        acc = fmaf(sm[4 * e4 + 3], v.w, acc);
    }
    g_gb[b * D_ + d] = acc;
}

// ---------------------------------------------------------------
// 5) Fused main GEMM + relu + W2 dot -> score[b,s]
//    One CTA per (b, 128-s tile); loops all 4 d-tiles internally
//    so the score reduction order is fixed (deterministic).
// ---------------------------------------------------------------
__global__ __launch_bounds__(256) void fused_score_kernel(
    const float* __restrict__ x, const float* __restrict__ W1,
    const float* __restrict__ W2, const float* __restrict__ b2)
{
    __shared__ float As[BK][BM];
    __shared__ float Bs[BK][132];
    __shared__ float red[BM][16];

    int b  = blockIdx.y;
    int s0 = blockIdx.x * BM;
    int tid = threadIdx.x;
    int tx = tid & 15, ty = tid >> 4;

    const float* xb = x + (size_t)b * D_ * S_;
    float score_acc = 0.f;  // owned by tid < 128 (row = tid)

    for (int nb = 0; nb < 4; ++nb) {
        int d0 = nb * BN;
        float c[8][8];
        #pragma unroll
        for (int i = 0; i < 8; i++)
            #pragma unroll
            for (int j = 0; j < 8; j++) c[i][j] = 0.f;

        for (int k0 = 0; k0 < D_; k0 += BK) {
            #pragma unroll
            for (int q = 0; q < 2; ++q) {
                int p = tid + q * 256;
                int e = p >> 5;
                int sc = (p & 31) << 2;
                float4 v = *(const float4*)(xb + (size_t)(k0 + e) * S_ + s0 + sc);
                *(float4*)(&As[e][sc]) = v;
            }
            #pragma unroll
            for (int q = 0; q < 2; ++q) {
                int p = tid + q * 256;
                int d = p >> 2;
                int e = (p & 3) << 2;
                float4 v = *(const float4*)(W1 + (size_t)(d0 + d) * TWO_D + k0 + e);
                Bs[e + 0][d] = v.x; Bs[e + 1][d] = v.y;
                Bs[e + 2][d] = v.z; Bs[e + 3][d] = v.w;
            }
            __syncthreads();
            #pragma unroll
            for (int kk = 0; kk < BK; ++kk) {
                float a[8], bb[8];
                #pragma unroll
                for (int i = 0; i < 8; i++) a[i] = As[kk][ty * 8 + i];
                #pragma unroll
                for (int j = 0; j < 8; j++) bb[j] = Bs[kk][tx * 8 + j];
                #pragma unroll
                for (int i = 0; i < 8; i++)
                    #pragma unroll
                    for (int j = 0; j < 8; j++)
                        c[i][j] = fmaf(a[i], bb[j], c[i][j]);
            }
            __syncthreads();
        }

        // epilogue: relu, dot with W2, reduce across tx
        #pragma unroll
        for (int i = 0; i < 8; i++) {
            int row = ty * 8 + i;
            int s = s0 + row;
            float part = 0.f;
            #pragma unroll
            for (int j = 0; j < 8; j++) {
                int d = d0 + tx * 8 + j;
                float v = c[i][j] + g_p1[(size_t)s * D_ + d] + g_gb[b * D_ + d];
                v = fmaxf(v, 0.f);
                part = fmaf(v, W2[d], part);
            }
            red[row][tx] = part;
        }
        __syncthreads();
        if (tid < BM) {
            float sum = 0.f;
            #pragma unroll
            for (int t = 0; t < 16; t++) sum += red[tid][t];
            score_acc += sum;
        }
        __syncthreads();
    }
    if (tid < BM)
        g_score[(size_t)b * S_ + s0 + tid] = score_acc + b2[0];
}

// ---------------------------------------------------------------
// 6) top-k (K=8) per batch; ties -> lower index (matches lax.top_k);
//    min-max normalization skipped (monotonic).
// ---------------------------------------------------------------
__global__ void topk_kernel() {
    __shared__ float sv[S_];
    __shared__ float rv[256];
    __shared__ int   ri[256];
    __shared__ int   chosen[K_];
    int b = blockIdx.x, tid = threadIdx.x;
    for (int i = tid; i < S_; i += 256) sv[i] = g_score[(size_t)b * S_ + i];
    __syncthreads();
    for (int k = 0; k < K_; k++) {
        float best = -INFINITY; int bi = S_;
        for (int i = tid; i < S_; i += 256) {
            float v = sv[i];
            if (v > best || (v == best && i < bi)) { best = v; bi = i; }
        }
        rv[tid] = best; ri[tid] = bi;
        __syncthreads();
        for (int off = 128; off > 0; off >>= 1) {
            if (tid < off) {
                float v2 = rv[tid + off]; int i2 = ri[tid + off];
                if (v2 > rv[tid] || (v2 == rv[tid] && i2 < ri[tid])) {
                    rv[tid] = v2; ri[tid] = i2;
                }
            }
            __syncthreads();
        }
        if (tid == 0) { chosen[k] = ri[0]; sv[ri[0]] = -INFINITY; }
        __syncthreads();
    }
    if (tid == 0) {
        #pragma unroll
        for (int a = 1; a < K_; a++) {        // insertion sort ascending
            int v = chosen[a]; int j = a - 1;
            while (j >= 0 && chosen[j] > v) { chosen[j + 1] = chosen[j]; j--; }
            chosen[j + 1] = v;
        }
        for (int k = 0; k < K_; k++) g_idx[b * K_ + k] = chosen[k];
    }
}

// ---------------------------------------------------------------
// 7) outputs
// ---------------------------------------------------------------
__global__ void zero_indices_kernel(float* __restrict__ out) {
    size_t i = (size_t)blockIdx.x * blockDim.x + threadIdx.x;  // float4 units
    ((float4*)out)[i] = make_float4(0.f, 0.f, 0.f, 0.f);
}

__global__ void scatter_ones_kernel(float* __restrict__ out) {
    int t = threadIdx.x;
    if (t < B_ * K_)
        out[(size_t)t * S_ + g_idx[t]] = 1.0f;   // out laid out [b][k][S]
}

__global__ void gather_selected_kernel(const float* __restrict__ x,
                                       float* __restrict__ out) {
    int bk = blockIdx.x;            // b*K + k
    int b = bk / K_;
    int s = g_idx[bk];
    int d = threadIdx.x;            // 512
    out[(size_t)bk * D_ + d] = x[(size_t)b * D_ * S_ + (size_t)d * S_ + s];
}

__global__ void transpose_kernel(const float* __restrict__ x,
                                 float* __restrict__ out) {
    __shared__ float tile[32][33];
    int b  = blockIdx.z;
    int d0 = blockIdx.y * 32;
    int s0 = blockIdx.x * 32;
    const float* xb = x   + (size_t)b * D_ * S_;
    float*       ob = out + (size_t)b * S_ * D_;
    #pragma unroll
    for (int r = 0; r < 32; r += 8)
        tile[threadIdx.y + r][threadIdx.x] =
            xb[(size_t)(d0 + threadIdx.y + r) * S_ + s0 + threadIdx.x];
    __syncthreads();
    #pragma unroll
    for (int r = 0; r < 32; r += 8)
        ob[(size_t)(s0 + threadIdx.y + r) * D_ + d0 + threadIdx.x] =
            tile[threadIdx.x][threadIdx.y + r];
}

// ---------------------------------------------------------------
extern "C" void kernel_launch(void* const* d_in, const int* in_sizes, int n_in,
                              void* d_out, int out_size) {
    const float* x  = (const float*)d_in[0];   // [B, D, S]
    const float* W1 = (const float*)d_in[1];   // [D, 2D]
    const float* b1 = (const float*)d_in[2];   // [D]
    const float* W2 = (const float*)d_in[3];   // [1, D]
    const float* b2 = (const float*)d_in[4];   // [1]
    float* out = (float*)d_out;

    const size_t IDX_SZ = (size_t)B_ * K_ * S_;   // 1,048,576
    const size_t SEL_SZ = (size_t)B_ * K_ * D_;   //   262,144
    float* out_idx  = out;
    float* out_sel  = out + IDX_SZ;
    float* out_feat = out + IDX_SZ + SEL_SZ;

    pe_fill_kernel<<<dim3(S_ / 256, D_), 256>>>();
    mean_kernel<<<(B_ * D_) / 8, 256>>>(x);
    p1_gemm_kernel<<<dim3(S_ / BM, D_ / BN), 256>>>(W1, b1);
    g_kernel<<<B_, 512>>>(W1);
    fused_score_kernel<<<dim3(S_ / BM, B_), 256>>>(x, W1, W2, b2);
    topk_kernel<<<B_, 256>>>();

    zero_indices_kernel<<<(unsigned)(IDX_SZ / 4 / 256), 256>>>(out_idx);
    scatter_ones_kernel<<<1, 512>>>(out_idx);
    gather_selected_kernel<<<B_ * K_, 512>>>(x, out_sel);
    transpose_kernel<<<dim3(S_ / 32, D_ / 32, B_), dim3(32, 8)>>>(x, out_feat);
}

// round 3
// speedup vs baseline: 2.9410x; 2.9410x over previous
#include <cuda_runtime.h>
#include <cuda_bf16.h>
#include <math.h>
#include <stdint.h>

#define B_    64
#define D_    512
#define S_    2048
#define K_    8
#define NCAND 16
#define TWO_D 1024

// ---------------- scratch (static device globals) ----------------
__device__ float g_peT [TWO_D * S_];               // PE^T [e][s]       (8 MB)
__device__ float g_part[4 * S_ * D_];              // p1 split-K parts  (16 MB)
__device__ float g_p1  [S_ * D_];                  // PE@W1^T + b1 [s][d]
__device__ float g_mpart[B_ * D_ * (S_ / 32)];     // mean partials (8 MB)
__device__ float g_mean[B_ * D_];
__device__ float g_gb  [B_ * D_];
__device__ float g_score[B_ * S_];
__device__ int   g_cand[B_ * NCAND];
__device__ float g_cs  [B_ * 2 * NCAND];           // rescore partials (2 halves)
__device__ int   g_idx [B_ * K_];
__device__ __nv_bfloat16 g_w1h[D_ * D_];           // W1[:, :512] bf16 [d][e]
__device__ float g_w1t [D_ * D_];                  // W1[:, :512] fp32 [e][d]
__device__ __nv_bfloat16 g_xT[(size_t)B_ * S_ * D_]; // x^T bf16 [b][s][e] (128MB)

// ---------------- PTX helpers ----------------
__device__ __forceinline__ uint32_t smem_u32(const void* p) {
    return (uint32_t)__cvta_generic_to_shared(p);
}
__device__ __forceinline__ void cp16(uint32_t dst, const void* src) {
    asm volatile("cp.async.cg.shared.global [%0], [%1], 16;" :: "r"(dst), "l"(src));
}
#define CP_COMMIT() asm volatile("cp.async.commit_group;" ::: "memory")
#define CP_WAIT(n)  asm volatile("cp.async.wait_group %0;" :: "n"(n) : "memory")

__device__ __forceinline__ void ldsm4(uint32_t* r, uint32_t a) {
    asm volatile("ldmatrix.sync.aligned.m8n8.x4.shared.b16 {%0,%1,%2,%3}, [%4];"
        : "=r"(r[0]), "=r"(r[1]), "=r"(r[2]), "=r"(r[3]) : "r"(a));
}
__device__ __forceinline__ void ldsm2(uint32_t* r, uint32_t a) {
    asm volatile("ldmatrix.sync.aligned.m8n8.x2.shared.b16 {%0,%1}, [%2];"
        : "=r"(r[0]), "=r"(r[1]) : "r"(a));
}
__device__ __forceinline__ void mma16816(float* c, const uint32_t* a, const uint32_t* b) {
    asm volatile(
        "mma.sync.aligned.m16n8k16.row.col.f32.bf16.bf16.f32 "
        "{%0,%1,%2,%3}, {%4,%5,%6,%7}, {%8,%9}, {%0,%1,%2,%3};"
        : "+f"(c[0]), "+f"(c[1]), "+f"(c[2]), "+f"(c[3])
        : "r"(a[0]), "r"(a[1]), "r"(a[2]), "r"(a[3]), "r"(b[0]), "r"(b[1]));
}

// ---------------------------------------------------------------
// 1) PE table (transposed: [e][s])
// ---------------------------------------------------------------
__global__ void pe_fill_kernel() {
    int s = blockIdx.x * blockDim.x + threadIdx.x;
    int i = blockIdx.y;
    float div = expf(-(float)(2 * i) * logf(10000.0f) / (float)TWO_D);
    float sv, cv;
    sincosf((float)s * div, &sv, &cv);
    g_peT[(size_t)(2 * i)     * S_ + s] = sv;
    g_peT[(size_t)(2 * i + 1) * S_ + s] = cv;
}

// ---------------------------------------------------------------
// 2) W1 first half -> bf16 [d][e] and fp32 transposed [e][d]
// ---------------------------------------------------------------
__global__ void w1_convert_kernel(const float* __restrict__ W1) {
    int i = blockIdx.x * blockDim.x + threadIdx.x;   // d*512 + e
    int d = i >> 9, e = i & 511;
    float v = W1[(size_t)d * TWO_D + e];
    g_w1h[i] = __float2bfloat16_rn(v);
    g_w1t[(size_t)e * D_ + d] = v;
}

// ---------------------------------------------------------------
// 3) Fused transpose: x[b][d][s] -> out_feat fp32 [b][s][d],
//    xT bf16 [b][s][e], and mean partial sums over 32-s tiles
// ---------------------------------------------------------------
__global__ void transpose_fused_kernel(const float* __restrict__ x,
                                       float* __restrict__ out_feat) {
    __shared__ float tile[32][33];
    int b  = blockIdx.z;
    int d0 = blockIdx.y * 32;
    int s0 = blockIdx.x * 32;
    const float* xb = x + (size_t)b * D_ * S_;
    #pragma unroll
    for (int r = 0; r < 32; r += 8)
        tile[threadIdx.y + r][threadIdx.x] =
            xb[(size_t)(d0 + threadIdx.y + r) * S_ + s0 + threadIdx.x];
    __syncthreads();
    float* ob = out_feat + (size_t)b * S_ * D_;
    __nv_bfloat16* xt = g_xT + (size_t)b * S_ * D_;
    #pragma unroll
    for (int r = 0; r < 32; r += 8) {
        int s = s0 + threadIdx.y + r;
        float v = tile[threadIdx.x][threadIdx.y + r];
        ob[(size_t)s * D_ + d0 + threadIdx.x] = v;
        xt[(size_t)s * D_ + d0 + threadIdx.x] = __float2bfloat16_rn(v);
    }
    if (threadIdx.y == 0) {
        float sum = 0.f;
        #pragma unroll
        for (int sl = 0; sl < 32; sl++) sum += tile[threadIdx.x][sl];
        g_mpart[((size_t)b * D_ + d0 + threadIdx.x) * (S_ / 32) + blockIdx.x] = sum;
    }
}

__global__ void mean_combine_kernel() {
    int i = blockIdx.x * blockDim.x + threadIdx.x;   // b*512+d
    float sum = 0.f;
    const float* p = g_mpart + (size_t)i * (S_ / 32);
    #pragma unroll
    for (int t = 0; t < S_ / 32; t++) sum += p[t];
    g_mean[i] = sum * (1.0f / S_);
}

// ---------------------------------------------------------------
// 4) g[b,d] = mean[b,:] . W1[d, 512:1024]
// ---------------------------------------------------------------
__global__ void g_kernel(const float* __restrict__ W1) {
    __shared__ float sm[D_];
    int b = blockIdx.x;
    for (int i = threadIdx.x; i < D_; i += 128) sm[i] = g_mean[b * D_ + i];
    __syncthreads();
    int d = blockIdx.y * 128 + threadIdx.x;
    const float4* w = (const float4*)(W1 + (size_t)d * TWO_D + D_);
    float acc = 0.f;
    #pragma unroll 8
    for (int e4 = 0; e4 < D_ / 4; e4++) {
        float4 v = w[e4];
        acc = fmaf(sm[4 * e4 + 0], v.x, acc);
        acc = fmaf(sm[4 * e4 + 1], v.y, acc);
        acc = fmaf(sm[4 * e4 + 2], v.z, acc);
        acc = fmaf(sm[4 * e4 + 3], v.w, acc);
    }
    g_gb[b * D_ + d] = acc;
}

// ---------------------------------------------------------------
// 5) p1 split-K SIMT fp32 GEMM + combine (exactness needed for rescore)
// ---------------------------------------------------------------
#define BM 128
#define BN 128
#define BK 16

__global__ __launch_bounds__(256) void p1_gemm_splitk_kernel(const float* __restrict__ W1) {
    __shared__ float As[BK][BM];
    __shared__ float Bs[BK][132];
    int s0 = blockIdx.x * BM;
    int d0 = blockIdx.y * BN;
    int z  = blockIdx.z;
    int tid = threadIdx.x;
    int tx = tid & 15, ty = tid >> 4;

    float c[8][8];
    #pragma unroll
    for (int i = 0; i < 8; i++)
        #pragma unroll
        for (int j = 0; j < 8; j++) c[i][j] = 0.f;

    for (int k0 = z * 256; k0 < z * 256 + 256; k0 += BK) {
        #pragma unroll
        for (int q = 0; q < 2; ++q) {
            int p = tid + q * 256;
            int e = p >> 5;
            int sc = (p & 31) << 2;
            float4 v = *(const float4*)(g_peT + (size_t)(k0 + e) * S_ + s0 + sc);
            *(float4*)(&As[e][sc]) = v;
        }
        #pragma unroll
        for (int q = 0; q < 2; ++q) {
            int p = tid + q * 256;
            int d = p >> 2;
            int e = (p & 3) << 2;
            float4 v = *(const float4*)(W1 + (size_t)(d0 + d) * TWO_D + k0 + e);
            Bs[e + 0][d] = v.x; Bs[e + 1][d] = v.y;
            Bs[e + 2][d] = v.z; Bs[e + 3][d] = v.w;
        }
        __syncthreads();
        #pragma unroll
        for (int kk = 0; kk < BK; ++kk) {
            float a[8], bb[8];
            #pragma unroll
            for (int i = 0; i < 8; i++) a[i] = As[kk][ty * 8 + i];
            #pragma unroll
            for (int j = 0; j < 8; j++) bb[j] = Bs[kk][tx * 8 + j];
            #pragma unroll
            for (int i = 0; i < 8; i++)
                #pragma unroll
                for (int j = 0; j < 8; j++)
                    c[i][j] = fmaf(a[i], bb[j], c[i][j]);
        }
        __syncthreads();
    }
    #pragma unroll
    for (int i = 0; i < 8; i++) {
        int s = s0 + ty * 8 + i;
        #pragma unroll
        for (int j = 0; j < 8; j++) {
            int d = d0 + tx * 8 + j;
            g_part[((size_t)z * S_ + s) * D_ + d] = c[i][j];
        }
    }
}

__global__ void p1_combine_kernel(const float* __restrict__ b1) {
    int idx = blockIdx.x * blockDim.x + threadIdx.x;  // s*512+d
    int d = idx & 511;
    float v = g_part[idx] + g_part[(size_t)S_ * D_ + idx]
            + g_part[2 * (size_t)S_ * D_ + idx] + g_part[3 * (size_t)S_ * D_ + idx];
    g_p1[idx] = v + b1[d];
}

// ---------------------------------------------------------------
// 6) MAIN: bf16 mma.sync GEMM + fused relu/W2 epilogue -> approx score
//    CTA: (s-tile 128, b). A resident (128x512 bf16), B double-buffered.
// ---------------------------------------------------------------
#define KC 64
#define SMEM_A  (128 * 128 * 8)     // 8 chunks x 16KB = 128KB
#define SMEM_B  (2 * 16384)
#define SMEM_DYN (SMEM_A + SMEM_B)  // 163840

__global__ void __launch_bounds__(256, 1)
fused_mma_kernel(const float* __restrict__ W2, const float* __restrict__ b2)
{
    extern __shared__ char dsm[];
    __shared__ float sW2[D_];
    __shared__ float sG[D_];
    __shared__ float sred[2][128];

    const uint32_t smA = smem_u32(dsm);
    const uint32_t smB = smA + SMEM_A;

    int tid = threadIdx.x;
    int lane = tid & 31;
    int w = tid >> 5;
    int wm = w & 3, wn = w >> 2;
    int b = blockIdx.y;
    int s0 = blockIdx.x * 128;

    for (int i = tid; i < D_; i += 256) {
        sW2[i] = W2[i];
        sG[i]  = g_gb[b * D_ + i];
    }

    const char* xA = (const char*)(g_xT + ((size_t)b * S_ + s0) * D_);

    // ---- prefetch: all 8 A chunks + B chunk 0 (group 0), B chunk 1 (group 1)
    #pragma unroll
    for (int q = 0; q < 32; q++) {
        int idx = tid + q * 256;            // 0..8191
        int kc = idx >> 10;
        int rem = idx & 1023;
        int row = rem >> 3, c = rem & 7;
        uint32_t dst = smA + kc * 16384 + row * 128 + (((c ^ (row & 7))) << 4);
        cp16(dst, xA + row * 1024 + kc * 128 + c * 16);
    }
    {   // B chunk 0 (nb=0, kc=0)
        const char* wB = (const char*)g_w1h;
        #pragma unroll
        for (int q = 0; q < 4; q++) {
            int idx = tid + q * 256;
            int row = idx >> 3, c = idx & 7;
            uint32_t dst = smB + row * 128 + (((c ^ (row & 7))) << 4);
            cp16(dst, wB + row * 1024 + c * 16);
        }
        CP_COMMIT();
        // B chunk 1 (nb=0, kc=1)
        #pragma unroll
        for (int q = 0; q < 4; q++) {
            int idx = tid + q * 256;
            int row = idx >> 3, c = idx & 7;
            uint32_t dst = smB + 16384 + row * 128 + (((c ^ (row & 7))) << 4);
            cp16(dst, wB + row * 1024 + 128 + c * 16);
        }
        CP_COMMIT();
    }

    float C[2][8][4];
    float acc[2][2] = {{0.f, 0.f}, {0.f, 0.f}};
    int quad = lane >> 2, qd = lane & 3;

    for (int t = 0; t < 32; ++t) {
        int kc = t & 7;
        int nb = t >> 3;
        if (kc == 0) {
            #pragma unroll
            for (int i = 0; i < 2; i++)
                #pragma unroll
                for (int j = 0; j < 8; j++)
                    #pragma unroll
                    for (int k = 0; k < 4; k++) C[i][j][k] = 0.f;
        }
        if (t >= 30) { CP_WAIT(0); } else { CP_WAIT(1); }
        __syncthreads();

        // ---- compute on A chunk kc, B buf (t&1)
        uint32_t Abase = smA + kc * 16384;
        uint32_t Bbase = smB + (t & 1) * 16384;
        #pragma unroll
        for (int kk = 0; kk < 4; kk++) {
            uint32_t a[2][4];
            #pragma unroll
            for (int i = 0; i < 2; i++) {
                int r = wm * 32 + i * 16 + (lane & 15);
                uint32_t ch = (uint32_t)((kk << 1) | (lane >> 4));
                ldsm4(a[i], Abase + r * 128 + ((ch ^ (uint32_t)(r & 7)) << 4));
            }
            uint32_t bf[8][2];
            #pragma unroll
            for (int j = 0; j < 8; j++) {
                int rn = wn * 64 + j * 8 + (lane & 7);
                uint32_t ch = (uint32_t)((kk << 1) | ((lane >> 3) & 1));
                ldsm2(bf[j], Bbase + rn * 128 + ((ch ^ (uint32_t)(rn & 7)) << 4));
            }
            #pragma unroll
            for (int i = 0; i < 2; i++)
                #pragma unroll
                for (int j = 0; j < 8; j++)
                    mma16816(C[i][j], a[i], bf[j]);
        }
        __syncthreads();

        // ---- prefetch B chunk t+2 into buf (t&1)
        if (t + 2 < 32) {
            int tn = t + 2;
            const char* wB = (const char*)(g_w1h + (size_t)(tn >> 3) * 128 * D_);
            int kcn = tn & 7;
            #pragma unroll
            for (int q = 0; q < 4; q++) {
                int idx = tid + q * 256;
                int row = idx >> 3, c = idx & 7;
                uint32_t dst = smB + (t & 1) * 16384 + row * 128 + (((c ^ (row & 7))) << 4);
                cp16(dst, wB + row * 1024 + kcn * 128 + c * 16);
            }
            CP_COMMIT();
        }

        // ---- epilogue at end of each d-tile
        if (kc == 7) {
            int d0 = nb * 128;
            #pragma unroll
            for (int i = 0; i < 2; i++) {
                int r0 = wm * 32 + i * 16 + quad;
                #pragma unroll
                for (int j = 0; j < 8; j++) {
                    int nl = wn * 64 + j * 8 + qd * 2;
                    int d = d0 + nl;
                    float w2x = sW2[d], w2y = sW2[d + 1];
                    float gx = sG[d],  gy = sG[d + 1];
                    const float* p = g_p1 + (size_t)(s0 + r0) * D_ + d;
                    float2 pA = *(const float2*)p;
                    float2 pB = *(const float2*)(p + 8 * D_);
                    float v0 = fmaxf(C[i][j][0] + pA.x + gx, 0.f);
                    float v1 = fmaxf(C[i][j][1] + pA.y + gy, 0.f);
                    float v2 = fmaxf(C[i][j][2] + pB.x + gx, 0.f);
                    float v3 = fmaxf(C[i][j][3] + pB.y + gy, 0.f);
                    acc[i][0] = fmaf(v0, w2x, fmaf(v1, w2y, acc[i][0]));
                    acc[i][1] = fmaf(v2, w2x, fmaf(v3, w2y, acc[i][1]));
                }
            }
        }
    }

    // ---- cross-lane + cross-warp score reduction
    #pragma unroll
    for (int i = 0; i < 2; i++)
        #pragma unroll
        for (int m = 0; m < 2; m++) {
            float v = acc[i][m];
            v += __shfl_xor_sync(0xffffffffu, v, 1);
            v += __shfl_xor_sync(0xffffffffu, v, 2);
            if (qd == 0) sred[wn][wm * 32 + i * 16 + m * 8 + quad] = v;
        }
    __syncthreads();
    if (tid < 128)
        g_score[(size_t)b * S_ + s0 + tid] = sred[0][tid] + sred[1][tid] + b2[0];
}

// ---------------------------------------------------------------
// 7) approx top-16 candidates per batch (ties -> lower index)
// ---------------------------------------------------------------
__global__ void topk_cand_kernel() {
    __shared__ float sv[S_];
    __shared__ float rv[256];
    __shared__ int   ri[256];
    int b = blockIdx.x, tid = threadIdx.x;
    for (int i = tid; i < S_; i += 256) sv[i] = g_score[(size_t)b * S_ + i];
    __syncthreads();
    for (int k = 0; k < NCAND; k++) {
        float best = -INFINITY; int bi = S_;
        for (int i = tid; i < S_; i += 256) {
            float v = sv[i];
            if (v > best || (v == best && i < bi)) { best = v; bi = i; }
        }
        rv[tid] = best; ri[tid] = bi;
        __syncthreads();
        for (int off = 128; off > 0; off >>= 1) {
            if (tid < off) {
                float v2 = rv[tid + off]; int i2 = ri[tid + off];
                if (v2 > rv[tid] || (v2 == rv[tid] && i2 < ri[tid])) {
                    rv[tid] = v2; ri[tid] = i2;
                }
            }
            __syncthreads();
        }
        if (tid == 0) { g_cand[b * NCAND + k] = ri[0]; sv[ri[0]] = -INFINITY; }
        __syncthreads();
    }
}

// ---------------------------------------------------------------
// 8) exact fp32 rescore of the 16 candidates (grid: (half, b))
// ---------------------------------------------------------------
__global__ __launch_bounds__(256) void rescore_kernel(
    const float* __restrict__ x, const float* __restrict__ W2)
{
    __shared__ float xcol[NCAND][D_];
    __shared__ int   scand[NCAND];
    __shared__ float wsum[8][NCAND];
    int h = blockIdx.x, b = blockIdx.y;
    int tid = threadIdx.x, lane = tid & 31, wid = tid >> 5;

    if (tid < NCAND) scand[tid] = g_cand[b * NCAND + tid];
    __syncthreads();
    for (int idx = tid; idx < NCAND * D_; idx += 256) {
        int c = idx >> 9, e = idx & 511;
        xcol[c][e] = x[((size_t)b * D_ + e) * S_ + scand[c]];
    }
    __syncthreads();

    int d = h * 256 + tid;
    float accv[NCAND];
    #pragma unroll
    for (int c = 0; c < NCAND; c++) accv[c] = 0.f;
    const float* wt = g_w1t + d;
    for (int e = 0; e < D_; e++) {
        float wv = wt[(size_t)e * D_];
        #pragma unroll
        for (int c = 0; c < NCAND; c++)
            accv[c] = fmaf(wv, xcol[c][e], accv[c]);
    }
    float w2v = W2[d];
    float gv  = g_gb[b * D_ + d];
    #pragma unroll
    for (int c = 0; c < NCAND; c++) {
        float hv = accv[c] + g_p1[(size_t)scand[c] * D_ + d] + gv;
        hv = fmaxf(hv, 0.f);
        float part = hv * w2v;
        #pragma unroll
        for (int off = 16; off > 0; off >>= 1)
            part += __shfl_xor_sync(0xffffffffu, part, off);
        if (lane == 0) wsum[wid][c] = part;
    }
    __syncthreads();
    if (tid < NCAND) {
        float s = 0.f;
        #pragma unroll
        for (int q = 0; q < 8; q++) s += wsum[q][tid];
        g_cs[(b * 2 + h) * NCAND + tid] = s;
    }
}

// ---------------------------------------------------------------
// 9) final exact top-8 selection + ascending sort
// ---------------------------------------------------------------
__global__ void final_select_kernel() {
    int b = blockIdx.x;
    if (threadIdx.x != 0) return;
    float sc[NCAND];
    int   id[NCAND];
    bool  used[NCAND];
    for (int c = 0; c < NCAND; c++) {
        sc[c] = g_cs[(b * 2) * NCAND + c] + g_cs[(b * 2 + 1) * NCAND + c];
        id[c] = g_cand[b * NCAND + c];
        used[c] = false;
    }
    int chosen[K_];
    for (int k = 0; k < K_; k++) {
        float best = -INFINITY; int bi = S_, bc = -1;
        for (int c = 0; c < NCAND; c++) {
            if (used[c]) continue;
            if (sc[c] > best || (sc[c] == best && id[c] < bi)) {
                best = sc[c]; bi = id[c]; bc = c;
            }
        }
        used[bc] = true;
        chosen[k] = bi;
    }
    for (int a = 1; a < K_; a++) {
        int v = chosen[a]; int j = a - 1;
        while (j >= 0 && chosen[j] > v) { chosen[j + 1] = chosen[j]; j--; }
        chosen[j + 1] = v;
    }
    for (int k = 0; k < K_; k++) g_idx[b * K_ + k] = chosen[k];
}

// ---------------------------------------------------------------
// 10) outputs
// ---------------------------------------------------------------
__global__ void zero_indices_kernel(float* __restrict__ out) {
    size_t i = (size_t)blockIdx.x * blockDim.x + threadIdx.x;
    ((float4*)out)[i] = make_float4(0.f, 0.f, 0.f, 0.f);
}
__global__ void scatter_ones_kernel(float* __restrict__ out) {
    int t = threadIdx.x;
    if (t < B_ * K_) out[(size_t)t * S_ + g_idx[t]] = 1.0f;
}
__global__ void gather_selected_kernel(const float* __restrict__ x,
                                       float* __restrict__ out) {
    int bk = blockIdx.x;
    int b = bk / K_;
    int s = g_idx[bk];
    int d = threadIdx.x;
    out[(size_t)bk * D_ + d] = x[(size_t)b * D_ * S_ + (size_t)d * S_ + s];
}

// ---------------------------------------------------------------
extern "C" void kernel_launch(void* const* d_in, const int* in_sizes, int n_in,
                              void* d_out, int out_size) {
    const float* x  = (const float*)d_in[0];
    const float* W1 = (const float*)d_in[1];
    const float* b1 = (const float*)d_in[2];
    const float* W2 = (const float*)d_in[3];
    const float* b2 = (const float*)d_in[4];
    float* out = (float*)d_out;

    const size_t IDX_SZ = (size_t)B_ * K_ * S_;
    const size_t SEL_SZ = (size_t)B_ * K_ * D_;
    float* out_idx  = out;
    float* out_sel  = out + IDX_SZ;
    float* out_feat = out + IDX_SZ + SEL_SZ;

    cudaFuncSetAttribute(fused_mma_kernel,
                         cudaFuncAttributeMaxDynamicSharedMemorySize, SMEM_DYN);

    pe_fill_kernel<<<dim3(S_ / 256, D_), 256>>>();
    w1_convert_kernel<<<(D_ * D_) / 256, 256>>>(W1);
    transpose_fused_kernel<<<dim3(S_ / 32, D_ / 32, B_), dim3(32, 8)>>>(x, out_feat);
    mean_combine_kernel<<<(B_ * D_) / 256, 256>>>();
    g_kernel<<<dim3(B_, 4), 128>>>(W1);
    p1_gemm_splitk_kernel<<<dim3(S_ / BM, D_ / BN, 4), 256>>>(W1);
    p1_combine_kernel<<<(S_ * D_) / 256, 256>>>(b1);
    fused_mma_kernel<<<dim3(S_ / 128, B_), 256, SMEM_DYN>>>(W2, b2);
    topk_cand_kernel<<<B_, 256>>>();
    rescore_kernel<<<dim3(2, B_), 256>>>(x, W2);
    final_select_kernel<<<B_, 32>>>();

    zero_indices_kernel<<<(unsigned)(IDX_SZ / 4 / 256), 256>>>(out_idx);
    scatter_ones_kernel<<<1, 512>>>(out_idx);
    gather_selected_kernel<<<B_ * K_, 512>>>(x, out_sel);
}

// round 5
// speedup vs baseline: 3.2834x; 1.1164x over previous
#include <cuda_runtime.h>
#include <cuda_bf16.h>
#include <cuda_fp16.h>
#include <math.h>
#include <stdint.h>

#define B_    64
#define D_    512
#define S_    2048
#define K_    8
#define NCAND 16
#define TWO_D 1024

// ---------------- scratch (static device globals) ----------------
__device__ __nv_bfloat16 g_pehi[S_ * TWO_D];   // PE hi [s][e] (4 MB)
__device__ __nv_bfloat16 g_pelo[S_ * TWO_D];   // PE lo [s][e] (4 MB)
__device__ __nv_bfloat16 g_w1h [D_ * TWO_D];   // W1 hi [d][e] full
__device__ __nv_bfloat16 g_w1lo[D_ * TWO_D];   // W1 lo [d][e] full
__device__ __half        g_w1f [D_ * D_];      // W1[:, :512] fp16 [d][e]
__device__ float g_w1t [D_ * D_];              // W1[:, :512] fp32 [e][d]
__device__ float g_w1t2[D_ * D_];              // W1[:, 512:] fp32 [e][d]
__device__ float g_p1  [S_ * D_];              // PE@W1^T + b1 [s][d]
__device__ float g_mpart[(S_ / 32) * B_ * D_]; // mean partials [tile][b*D+d]
__device__ float g_gb  [B_ * D_];
__device__ float g_score[B_ * S_];
__device__ int   g_cand[B_ * NCAND];
__device__ float g_cs  [B_ * 2 * NCAND];
__device__ int   g_idx [B_ * K_];

// ---------------- PTX helpers ----------------
__device__ __forceinline__ uint32_t smem_u32(const void* p) {
    return (uint32_t)__cvta_generic_to_shared(p);
}
__device__ __forceinline__ uint32_t h2u(__half2 h) {
    union { __half2 h; uint32_t u; } cvt;
    cvt.h = h;
    return cvt.u;
}
__device__ __forceinline__ void cp16(uint32_t dst, const void* src) {
    asm volatile("cp.async.cg.shared.global [%0], [%1], 16;" :: "r"(dst), "l"(src));
}
#define CP_COMMIT() asm volatile("cp.async.commit_group;" ::: "memory")
#define CP_WAIT(n)  asm volatile("cp.async.wait_group %0;" :: "n"(n) : "memory")

__device__ __forceinline__ void ldsm4(uint32_t* r, uint32_t a) {
    asm volatile("ldmatrix.sync.aligned.m8n8.x4.shared.b16 {%0,%1,%2,%3}, [%4];"
        : "=r"(r[0]), "=r"(r[1]), "=r"(r[2]), "=r"(r[3]) : "r"(a));
}
__device__ __forceinline__ void ldsm4t(uint32_t* r, uint32_t a) {
    asm volatile("ldmatrix.sync.aligned.m8n8.x4.trans.shared.b16 {%0,%1,%2,%3}, [%4];"
        : "=r"(r[0]), "=r"(r[1]), "=r"(r[2]), "=r"(r[3]) : "r"(a));
}
__device__ __forceinline__ void ldsm2(uint32_t* r, uint32_t a) {
    asm volatile("ldmatrix.sync.aligned.m8n8.x2.shared.b16 {%0,%1}, [%2];"
        : "=r"(r[0]), "=r"(r[1]) : "r"(a));
}
// bf16 inputs, fp32 accum (exact p1 path)
__device__ __forceinline__ void mma_bf_f32(float* c, const uint32_t* a, const uint32_t* b) {
    asm volatile(
        "mma.sync.aligned.m16n8k16.row.col.f32.bf16.bf16.f32 "
        "{%0,%1,%2,%3}, {%4,%5,%6,%7}, {%8,%9}, {%0,%1,%2,%3};"
        : "+f"(c[0]), "+f"(c[1]), "+f"(c[2]), "+f"(c[3])
        : "r"(a[0]), "r"(a[1]), "r"(a[2]), "r"(a[3]), "r"(b[0]), "r"(b[1]));
}
// fp16 inputs, fp16 accum (fast approx path)
__device__ __forceinline__ void mma_h_h(uint32_t* c, const uint32_t* a, const uint32_t* b) {
    asm volatile(
        "mma.sync.aligned.m16n8k16.row.col.f16.f16.f16.f16 "
        "{%0,%1}, {%2,%3,%4,%5}, {%6,%7}, {%0,%1};"
        : "+r"(c[0]), "+r"(c[1])
        : "r"(a[0]), "r"(a[1]), "r"(a[2]), "r"(a[3]), "r"(b[0]), "r"(b[1]));
}

// ---------------------------------------------------------------
// 1) merged PE (hi/lo bf16, [s][e]) + W1 conversions
// ---------------------------------------------------------------
__global__ void pew1_kernel(const float* __restrict__ W1) {
    int bx = blockIdx.x;
    if (bx < S_) {
        int s = bx, i = threadIdx.x;  // i = 0..511, e = 2i, 2i+1
        float div = expf(-(float)(2 * i) * (logf(10000.0f) / (float)TWO_D));
        float sv, cv;
        sincosf((float)s * div, &sv, &cv);
        __nv_bfloat16 hs = __float2bfloat16_rn(sv);
        __nv_bfloat16 hc = __float2bfloat16_rn(cv);
        __nv_bfloat16 ls = __float2bfloat16_rn(sv - __bfloat162float(hs));
        __nv_bfloat16 lc = __float2bfloat16_rn(cv - __bfloat162float(hc));
        ((__nv_bfloat162*)g_pehi)[(size_t)s * (TWO_D / 2) + i] =
            __nv_bfloat162(hs, hc);
        ((__nv_bfloat162*)g_pelo)[(size_t)s * (TWO_D / 2) + i] =
            __nv_bfloat162(ls, lc);
    } else {
        int idx = (bx - S_) * 512 + threadIdx.x;    // d*1024 + e
        int d = idx >> 10, e = idx & 1023;
        float v = W1[idx];
        __nv_bfloat16 h = __float2bfloat16_rn(v);
        g_w1h[idx]  = h;
        g_w1lo[idx] = __float2bfloat16_rn(v - __bfloat162float(h));
        if (e < 512) {
            g_w1f[d * 512 + e] = __float2half_rn(v);
            g_w1t[(size_t)e * D_ + d] = v;
        } else {
            g_w1t2[(size_t)(e - 512) * D_ + d] = v;
        }
    }
}

// ---------------------------------------------------------------
// 2) p1 via hi/lo bf16 MMA (3 products, fp32 accum): effectively exact.
//    CTA: (s-tile 128, d-tile 128). K = 1024.
// ---------------------------------------------------------------
#define P1_SMEM (2 * 65536)

__global__ void __launch_bounds__(256, 1)
p1_mma_kernel(const float* __restrict__ b1) {
    extern __shared__ char dsm[];
    uint32_t smb = smem_u32(dsm);
    int tid = threadIdx.x, lane = tid & 31, w = tid >> 5;
    int wm = w & 3, wn = w >> 2;
    int quad = lane >> 2, qd = lane & 3;
    int s0 = blockIdx.x * 128;
    int d0b = blockIdx.y * 128;

    const char* Ah = (const char*)g_pehi + (size_t)s0 * 2048;
    const char* Al = (const char*)g_pelo + (size_t)s0 * 2048;
    const char* Bh = (const char*)g_w1h + (size_t)d0b * 2048;
    const char* Bl = (const char*)g_w1lo + (size_t)d0b * 2048;

    // prefetch chunk t into buffer t&1: [Ahi|Alo|Bhi|Blo] 16KB each
    #define P1_PF(t) do { \
        int p_ = (t) & 1; \
        uint32_t base_ = smb + p_ * 65536; \
        _Pragma("unroll") \
        for (int q = 0; q < 4; q++) { \
            int idx = tid + q * 256; \
            int row = idx >> 3, c = idx & 7; \
            uint32_t off = row * 128 + (((c ^ (row & 7))) << 4); \
            size_t src = (size_t)row * 2048 + (size_t)(t) * 128 + c * 16; \
            cp16(base_ + off,          Ah + src); \
            cp16(base_ + 16384 + off,  Al + src); \
            cp16(base_ + 32768 + off,  Bh + src); \
            cp16(base_ + 49152 + off,  Bl + src); \
        } \
        CP_COMMIT(); \
    } while (0)

    P1_PF(0);
    P1_PF(1);

    float C[2][8][4];
    #pragma unroll
    for (int i = 0; i < 2; i++)
        #pragma unroll
        for (int j = 0; j < 8; j++)
            #pragma unroll
            for (int k = 0; k < 4; k++) C[i][j][k] = 0.f;

    for (int t = 0; t < 16; ++t) {
        if (t >= 14) { CP_WAIT(0); } else { CP_WAIT(1); }
        __syncthreads();
        uint32_t bA = smb + (t & 1) * 65536;
        #pragma unroll
        for (int kk = 0; kk < 4; kk++) {
            uint32_t ah[2][4], al[2][4];
            #pragma unroll
            for (int i = 0; i < 2; i++) {
                int r = wm * 32 + i * 16 + (lane & 15);
                uint32_t ch = (uint32_t)((kk << 1) | (lane >> 4));
                uint32_t off = r * 128 + ((ch ^ (uint32_t)(r & 7)) << 4);
                ldsm4(ah[i], bA + off);
                ldsm4(al[i], bA + 16384 + off);
            }
            uint32_t bh[8][2], bl[8][2];
            #pragma unroll
            for (int j = 0; j < 8; j++) {
                int rn = wn * 64 + j * 8 + (lane & 7);
                uint32_t ch = (uint32_t)((kk << 1) | ((lane >> 3) & 1));
                uint32_t off = rn * 128 + ((ch ^ (uint32_t)(rn & 7)) << 4);
                ldsm2(bh[j], bA + 32768 + off);
                ldsm2(bl[j], bA + 49152 + off);
            }
            #pragma unroll
            for (int i = 0; i < 2; i++)
                #pragma unroll
                for (int j = 0; j < 8; j++) {
                    mma_bf_f32(C[i][j], ah[i], bh[j]);
                    mma_bf_f32(C[i][j], ah[i], bl[j]);
                    mma_bf_f32(C[i][j], al[i], bh[j]);
                }
        }
        __syncthreads();
        if (t + 2 < 16) P1_PF(t + 2);
    }

    #pragma unroll
    for (int i = 0; i < 2; i++) {
        int sg = s0 + wm * 32 + i * 16 + quad;
        #pragma unroll
        for (int j = 0; j < 8; j++) {
            int d = d0b + wn * 64 + j * 8 + qd * 2;
            float2 bv = *(const float2*)(b1 + d);
            *(float2*)(g_p1 + (size_t)sg * D_ + d) =
                make_float2(C[i][j][0] + bv.x, C[i][j][1] + bv.y);
            *(float2*)(g_p1 + (size_t)(sg + 8) * D_ + d) =
                make_float2(C[i][j][2] + bv.x, C[i][j][3] + bv.y);
        }
    }
    #undef P1_PF
}

// ---------------------------------------------------------------
// 3) transpose: x[b][d][s] -> out_feat [b][s][d] + mean partials
// ---------------------------------------------------------------
__global__ void transpose_fused_kernel(const float* __restrict__ x,
                                       float* __restrict__ out_feat) {
    __shared__ float tile[32][33];
    int b  = blockIdx.z;
    int d0 = blockIdx.y * 32;
    int s0 = blockIdx.x * 32;
    const float* xb = x + (size_t)b * D_ * S_;
    #pragma unroll
    for (int r = 0; r < 32; r += 8)
        tile[threadIdx.y + r][threadIdx.x] =
            xb[(size_t)(d0 + threadIdx.y + r) * S_ + s0 + threadIdx.x];
    __syncthreads();
    float* ob = out_feat + (size_t)b * S_ * D_;
    #pragma unroll
    for (int r = 0; r < 32; r += 8) {
        int s = s0 + threadIdx.y + r;
        ob[(size_t)s * D_ + d0 + threadIdx.x] = tile[threadIdx.x][threadIdx.y + r];
    }
    if (threadIdx.y == 0) {
        float sum = 0.f;
        #pragma unroll
        for (int sl = 0; sl < 32; sl++) sum += tile[threadIdx.x][sl];
        g_mpart[(size_t)blockIdx.x * (B_ * D_) + b * D_ + d0 + threadIdx.x] = sum;
    }
}

// ---------------------------------------------------------------
// 4) merged mean-combine + g[b,d] = mean[b,:] . W1[d, 512:1024]
// ---------------------------------------------------------------
__global__ void meang_kernel() {
    __shared__ float sm[D_];
    int b = blockIdx.x, d = threadIdx.x;  // 512 threads
    float s = 0.f;
    #pragma unroll
    for (int t = 0; t < S_ / 32; t++)
        s += g_mpart[(size_t)t * (B_ * D_) + b * D_ + d];
    sm[d] = s * (1.0f / S_);
    __syncthreads();
    float acc = 0.f;
    for (int e = 0; e < D_; e++)
        acc = fmaf(sm[e], g_w1t2[(size_t)e * D_ + d], acc);
    g_gb[b * D_ + d] = acc;
}

// ---------------------------------------------------------------
// 5) MAIN: fp16 mma GEMM (f16 accum) + fused relu/W2 epilogue.
//    CTA: (s-tile 128, b). A = x^T chunk-resident (converted in-kernel),
//    B = W1 fp16 streamed double-buffered. A-load pipelined under nb=0.
// ---------------------------------------------------------------
#define SMEM_A   (8 * 16384)        // 128 KB: 8 chunks of [64e][128s] fp16
#define SMEM_B   (2 * 16384)
#define SMEM_DYN (SMEM_A + SMEM_B)  // 160 KB

__global__ void __launch_bounds__(256, 1)
fused_mma_kernel(const float* __restrict__ x, const float* __restrict__ W2,
                 const float* __restrict__ b2)
{
    extern __shared__ char dsm[];
    __shared__ float sW2[D_];
    __shared__ float sG[D_];
    __shared__ float sred[2][128];

    const uint32_t smA = smem_u32(dsm);
    const uint32_t smB = smA + SMEM_A;

    int tid = threadIdx.x;
    int lane = tid & 31;
    int w = tid >> 5;
    int wm = w & 3, wn = w >> 2;
    int quad = lane >> 2, qd = lane & 3;
    int b = blockIdx.y;
    int s0 = blockIdx.x * 128;

    for (int i = tid; i < D_; i += 256) {
        sW2[i] = W2[i];
        sG[i]  = g_gb[b * D_ + i];
    }

    const float* xA = x + (size_t)b * D_ * S_ + s0;

    // B prefetch macro: chunk index tc (0..31), buffer tc&1
    #define B_PF(tc) do { \
        const char* wB_ = (const char*)(g_w1f + (size_t)((tc) >> 3) * 128 * 512); \
        int kcn_ = (tc) & 7; \
        _Pragma("unroll") \
        for (int q = 0; q < 4; q++) { \
            int idx = tid + q * 256; \
            int row = idx >> 3, c = idx & 7; \
            uint32_t dst = smB + ((tc) & 1) * 16384 + row * 128 + (((c ^ (row & 7))) << 4); \
            cp16(dst, wB_ + row * 1024 + kcn_ * 128 + c * 16); \
        } \
        CP_COMMIT(); \
    } while (0)

    B_PF(0);
    B_PF(1);

    // A chunk LDG into registers / STS (fp32 -> fp16) helpers
    float4 st[8];
    #define A_LDG(kc) do { \
        _Pragma("unroll") \
        for (int q = 0; q < 8; q++) { \
            int idx = tid + q * 256; \
            int e = (kc) * 64 + (idx >> 5), c4 = idx & 31; \
            st[q] = __ldg((const float4*)(xA + (size_t)e * S_ + c4 * 4)); \
        } \
    } while (0)
    #define A_STS(kc) do { \
        _Pragma("unroll") \
        for (int q = 0; q < 8; q++) { \
            int idx = tid + q * 256; \
            int el = idx >> 5, c4 = idx & 31; \
            __half2 h01 = __floats2half2_rn(st[q].x, st[q].y); \
            __half2 h23 = __floats2half2_rn(st[q].z, st[q].w); \
            uint32_t off = (uint32_t)((kc) * 16384 + el * 256 + \
                (((c4 >> 1) ^ (el & 7)) << 4) + (c4 & 1) * 8); \
            *(uint2*)(dsm + off) = make_uint2(h2u(h01), h2u(h23)); \
        } \
    } while (0)

    A_LDG(0);

    uint32_t C[2][8][2];
    float acc[2][2] = {{0.f, 0.f}, {0.f, 0.f}};

    for (int t = 0; t < 32; ++t) {
        int kc = t & 7;
        int nb = t >> 3;
        if (kc == 0) {
            #pragma unroll
            for (int i = 0; i < 2; i++)
                #pragma unroll
                for (int j = 0; j < 8; j++) { C[i][j][0] = 0u; C[i][j][1] = 0u; }
        }
        if (t < 8) A_STS(t);
        if (t >= 30) { CP_WAIT(0); } else { CP_WAIT(1); }
        __syncthreads();
        if (t < 7) A_LDG(t + 1);

        uint32_t Abase = smA + kc * 16384;
        uint32_t Bbase = smB + (t & 1) * 16384;
        #pragma unroll
        for (int kk = 0; kk < 4; kk++) {
            uint32_t a[2][4];
            #pragma unroll
            for (int i = 0; i < 2; i++) {
                int s0m = wm * 32 + i * 16;
                int row = kk * 16 + ((lane >> 4) << 3) + (lane & 7);
                int col16 = (s0m >> 3) + ((lane >> 3) & 1);
                ldsm4t(a[i], Abase + row * 256 +
                             (((uint32_t)(col16 ^ (row & 7))) << 4));
            }
            uint32_t bf[8][2];
            #pragma unroll
            for (int j = 0; j < 8; j++) {
                int rn = wn * 64 + j * 8 + (lane & 7);
                uint32_t ch = (uint32_t)((kk << 1) | ((lane >> 3) & 1));
                ldsm2(bf[j], Bbase + rn * 128 + ((ch ^ (uint32_t)(rn & 7)) << 4));
            }
            #pragma unroll
            for (int i = 0; i < 2; i++)
                #pragma unroll
                for (int j = 0; j < 8; j++)
                    mma_h_h(C[i][j], a[i], bf[j]);
        }
        __syncthreads();
        if (t + 2 < 32) B_PF(t + 2);

        if (kc == 7) {
            int d0 = nb * 128;
            #pragma unroll
            for (int i = 0; i < 2; i++) {
                int r0 = wm * 32 + i * 16 + quad;
                #pragma unroll
                for (int j = 0; j < 8; j++) {
                    int d = d0 + wn * 64 + j * 8 + qd * 2;
                    float w2x = sW2[d], w2y = sW2[d + 1];
                    float gx = sG[d],  gy = sG[d + 1];
                    const float* p = g_p1 + (size_t)(s0 + r0) * D_ + d;
                    float2 pA = *(const float2*)p;
                    float2 pB = *(const float2*)(p + 8 * D_);
                    __half2 ha = *(__half2*)&C[i][j][0];
                    __half2 hb = *(__half2*)&C[i][j][1];
                    float v0 = fmaxf(__low2float(ha)  + pA.x + gx, 0.f);
                    float v1 = fmaxf(__high2float(ha) + pA.y + gy, 0.f);
                    float v2 = fmaxf(__low2float(hb)  + pB.x + gx, 0.f);
                    float v3 = fmaxf(__high2float(hb) + pB.y + gy, 0.f);
                    acc[i][0] = fmaf(v0, w2x, fmaf(v1, w2y, acc[i][0]));
                    acc[i][1] = fmaf(v2, w2x, fmaf(v3, w2y, acc[i][1]));
                }
            }
        }
    }
    #undef B_PF
    #undef A_LDG
    #undef A_STS

    #pragma unroll
    for (int i = 0; i < 2; i++)
        #pragma unroll
        for (int m = 0; m < 2; m++) {
            float v = acc[i][m];
            v += __shfl_xor_sync(0xffffffffu, v, 1);
            v += __shfl_xor_sync(0xffffffffu, v, 2);
            if (qd == 0) sred[wn][wm * 32 + i * 16 + m * 8 + quad] = v;
        }
    __syncthreads();
    if (tid < 128)
        g_score[(size_t)b * S_ + s0 + tid] = sred[0][tid] + sred[1][tid] + b2[0];
}

// ---------------------------------------------------------------
// 6) approx top-16 candidates per batch (ties -> lower index)
// ---------------------------------------------------------------
__global__ void topk_cand_kernel() {
    __shared__ float sv[S_];
    __shared__ float rv[256];
    __shared__ int   ri[256];
    int b = blockIdx.x, tid = threadIdx.x;
    for (int i = tid; i < S_; i += 256) sv[i] = g_score[(size_t)b * S_ + i];
    __syncthreads();
    for (int k = 0; k < NCAND; k++) {
        float best = -INFINITY; int bi = S_;
        for (int i = tid; i < S_; i += 256) {
            float v = sv[i];
            if (v > best || (v == best && i < bi)) { best = v; bi = i; }
        }
        rv[tid] = best; ri[tid] = bi;
        __syncthreads();
        for (int off = 128; off > 0; off >>= 1) {
            if (tid < off) {
                float v2 = rv[tid + off]; int i2 = ri[tid + off];
                if (v2 > rv[tid] || (v2 == rv[tid] && i2 < ri[tid])) {
                    rv[tid] = v2; ri[tid] = i2;
                }
            }
            __syncthreads();
        }
        if (tid == 0) { g_cand[b * NCAND + k] = ri[0]; sv[ri[0]] = -INFINITY; }
        __syncthreads();
    }
}

// ---------------------------------------------------------------
// 7) exact fp32 rescore of 16 candidates (grid: (half, b))
// ---------------------------------------------------------------
__global__ __launch_bounds__(256) void rescore_kernel(
    const float* __restrict__ x, const float* __restrict__ W2)
{
    __shared__ float xcol[NCAND][D_];
    __shared__ int   scand[NCAND];
    __shared__ float wsum[8][NCAND];
    int h = blockIdx.x, b = blockIdx.y;
    int tid = threadIdx.x, lane = tid & 31, wid = tid >> 5;

    if (tid < NCAND) scand[tid] = g_cand[b * NCAND + tid];
    __syncthreads();
    for (int idx = tid; idx < NCAND * D_; idx += 256) {
        int c = idx >> 9, e = idx & 511;
        xcol[c][e] = x[((size_t)b * D_ + e) * S_ + scand[c]];
    }
    __syncthreads();

    int d = h * 256 + tid;
    float accv[NCAND];
    #pragma unroll
    for (int c = 0; c < NCAND; c++) accv[c] = 0.f;
    const float* wt = g_w1t + d;
    for (int e = 0; e < D_; e++) {
        float wv = wt[(size_t)e * D_];
        #pragma unroll
        for (int c = 0; c < NCAND; c++)
            accv[c] = fmaf(wv, xcol[c][e], accv[c]);
    }
    float w2v = W2[d];
    float gv  = g_gb[b * D_ + d];
    #pragma unroll
    for (int c = 0; c < NCAND; c++) {
        float hv = accv[c] + g_p1[(size_t)scand[c] * D_ + d] + gv;
        hv = fmaxf(hv, 0.f);
        float part = hv * w2v;
        #pragma unroll
        for (int off = 16; off > 0; off >>= 1)
            part += __shfl_xor_sync(0xffffffffu, part, off);
        if (lane == 0) wsum[wid][c] = part;
    }
    __syncthreads();
    if (tid < NCAND) {
        float s = 0.f;
        #pragma unroll
        for (int q = 0; q < 8; q++) s += wsum[q][tid];
        g_cs[(b * 2 + h) * NCAND + tid] = s;
    }
}

// ---------------------------------------------------------------
// 8) final exact top-8 + ascending sort
// ---------------------------------------------------------------
__global__ void final_select_kernel() {
    int b = blockIdx.x;
    if (threadIdx.x != 0) return;
    float sc[NCAND];
    int   id[NCAND];
    bool  used[NCAND];
    for (int c = 0; c < NCAND; c++) {
        sc[c] = g_cs[(b * 2) * NCAND + c] + g_cs[(b * 2 + 1) * NCAND + c];
        id[c] = g_cand[b * NCAND + c];
        used[c] = false;
    }
    int chosen[K_];
    for (int k = 0; k < K_; k++) {
        float best = -INFINITY; int bi = S_, bc = -1;
        for (int c = 0; c < NCAND; c++) {
            if (used[c]) continue;
            if (sc[c] > best || (sc[c] == best && id[c] < bi)) {
                best = sc[c]; bi = id[c]; bc = c;
            }
        }
        used[bc] = true;
        chosen[k] = bi;
    }
    for (int a = 1; a < K_; a++) {
        int v = chosen[a]; int j = a - 1;
        while (j >= 0 && chosen[j] > v) { chosen[j + 1] = chosen[j]; j--; }
        chosen[j + 1] = v;
    }
    for (int k = 0; k < K_; k++) g_idx[b * K_ + k] = chosen[k];
}

// ---------------------------------------------------------------
// 9) outputs
// ---------------------------------------------------------------
__global__ void zero_indices_kernel(float* __restrict__ out) {
    size_t i = (size_t)blockIdx.x * blockDim.x + threadIdx.x;
    ((float4*)out)[i] = make_float4(0.f, 0.f, 0.f, 0.f);
}
__global__ void scatter_ones_kernel(float* __restrict__ out) {
    int t = threadIdx.x;
    if (t < B_ * K_) out[(size_t)t * S_ + g_idx[t]] = 1.0f;
}
__global__ void gather_selected_kernel(const float* __restrict__ x,
                                       float* __restrict__ out) {
    int bk = blockIdx.x;
    int b = bk / K_;
    int s = g_idx[bk];
    int d = threadIdx.x;
    out[(size_t)bk * D_ + d] = x[(size_t)b * D_ * S_ + (size_t)d * S_ + s];
}

// ---------------------------------------------------------------
extern "C" void kernel_launch(void* const* d_in, const int* in_sizes, int n_in,
                              void* d_out, int out_size) {
    const float* x  = (const float*)d_in[0];
    const float* W1 = (const float*)d_in[1];
    const float* b1 = (const float*)d_in[2];
    const float* W2 = (const float*)d_in[3];
    const float* b2 = (const float*)d_in[4];
    float* out = (float*)d_out;

    const size_t IDX_SZ = (size_t)B_ * K_ * S_;
    const size_t SEL_SZ = (size_t)B_ * K_ * D_;
    float* out_idx  = out;
    float* out_sel  = out + IDX_SZ;
    float* out_feat = out + IDX_SZ + SEL_SZ;

    cudaFuncSetAttribute(fused_mma_kernel,
                         cudaFuncAttributeMaxDynamicSharedMemorySize, SMEM_DYN);
    cudaFuncSetAttribute(p1_mma_kernel,
                         cudaFuncAttributeMaxDynamicSharedMemorySize, P1_SMEM);

    pew1_kernel<<<S_ + (D_ * TWO_D) / 512, 512>>>(W1);                        // 1
    p1_mma_kernel<<<dim3(S_ / 128, D_ / 128), 256, P1_SMEM>>>(b1);            // 2
    zero_indices_kernel<<<(unsigned)(IDX_SZ / 4 / 256), 256>>>(out_idx);      // 3
    transpose_fused_kernel<<<dim3(S_ / 32, D_ / 32, B_), dim3(32, 8)>>>(x, out_feat); // 4 (profiled)
    meang_kernel<<<B_, 512>>>();                                              // 5
    fused_mma_kernel<<<dim3(S_ / 128, B_), 256, SMEM_DYN>>>(x, W2, b2);       // 6
    topk_cand_kernel<<<B_, 256>>>();                                          // 7
    rescore_kernel<<<dim3(2, B_), 256>>>(x, W2);                              // 8
    final_select_kernel<<<B_, 32>>>();                                        // 9
    scatter_ones_kernel<<<1, 512>>>(out_idx);                                 // 10
    gather_selected_kernel<<<B_ * K_, 512>>>(x, out_sel);                     // 11
}